// round 3
// baseline (speedup 1.0000x reference)
#include <cuda_runtime.h>
#include <math.h>

#define BATCH 8
#define NNODE 20000
#define FEATD 256
#define HDIM  512
#define HCW   4096          // B*H
#define F1D   1024
#define KO1   32
#define KO2   10
#define EPSBN 1e-5f

typedef unsigned long long ull;

// ---------------- scratch (static device globals; no allocation) ----------------
__device__ float  g_h1[(size_t)BATCH * NNODE * HDIM];   // 327 MB
__device__ float  g_hc[(size_t)NNODE * HCW];            // 327 MB
__device__ float  g_f [(size_t)NNODE * F1D];            // 82 MB
__device__ float  g_f2[(size_t)NNODE * KO1];
__device__ double g_sum1[HCW], g_sq1[HCW];
__device__ float  g_scale1[HCW], g_shift1[HCW];
__device__ double g_sum2[HCW], g_sq2[HCW];
__device__ float  g_scale2[HCW], g_shift2[HCW];

// ---------------- packed f32x2 helpers ----------------
__device__ __forceinline__ ull pk2(float x, float y) {
    ull r; asm("mov.b64 %0, {%1, %2};" : "=l"(r) : "f"(x), "f"(y)); return r;
}
__device__ __forceinline__ float2 up2(ull v) {
    float2 f; asm("mov.b64 {%0, %1}, %2;" : "=f"(f.x), "=f"(f.y) : "l"(v)); return f;
}
__device__ __forceinline__ ull fma2(ull a, ull b, ull c) {
    ull d; asm("fma.rn.f32x2 %0, %1, %2, %3;" : "=l"(d) : "l"(a), "l"(b), "l"(c)); return d;
}

// ---------------- tiled SGEMM, packed f32x2 math path ----------------
// C[M x N] = epi( transformA(A[M x K]) * B[K x N] + bias[N] )
// transformA: a' = relu(scale[k]*a + shift[k]) when tScale != nullptr
#define BM 128
#define BN 128
#define BK 16
#define GEMM_THREADS 256

__global__ void __launch_bounds__(GEMM_THREADS, 2)
sgemm2_kernel(const float* __restrict__ A, long aBatch, int lda,
              const float* __restrict__ B, long bBatch, int ldb,
              const float* __restrict__ bias, int biasBatch,
              float* __restrict__ C, long cBatch, int ldc,
              const float* __restrict__ tScale, const float* __restrict__ tShift, int tBatch,
              int M, int N, int K, int reluEpi)
{
    // As: plain, padded rows (132 floats = 528B, 16B aligned)
    // Bs: duplicated pairs {v,v,w,w}, 1024B rows, XOR-swizzled 16B quads
    __shared__ float As[2][BK][BM + 4];
    __shared__ float Bs[2][BK][BN * 2];

    const int bz = blockIdx.z;
    A += (long)bz * aBatch;
    B += (long)bz * bBatch;
    C += (long)bz * cBatch;
    const float* biasp = bias + (long)bz * biasBatch;
    const float* tS = tScale ? tScale + (long)bz * tBatch : nullptr;
    const float* tH = tShift ? tShift + (long)bz * tBatch : nullptr;

    const int n0 = blockIdx.x * BN;       // n fast -> L2 reuse of A strip
    const int m0 = blockIdx.y * BM;
    const int t  = threadIdx.x;
    const int tx = t & 15;                // 16 groups x 8 cols
    const int ty = t >> 4;                // 16 groups x 8 rows

    // staging indices
    const int a_r  = t >> 2;              // 0..63
    const int a_kq = (t & 3) * 4;         // k sub-offset
    const int b_k  = t >> 5;              // 0..7
    const int b_n4 = (t & 31) * 4;

    ull acc[4][8];
#pragma unroll
    for (int i = 0; i < 4; i++)
#pragma unroll
        for (int j = 0; j < 8; j++) acc[i][j] = 0ull;

    float4 avA, avB, bv0, bv1;            // prefetch registers

    // ---- load helpers (macros to keep regs tight) ----
#define LDG_STAGE(k0)                                                            \
    {                                                                            \
        float4 ts0, th0;                                                         \
        if (tS) { ts0 = *(const float4*)&tS[(k0) + a_kq];                        \
                  th0 = *(const float4*)&tH[(k0) + a_kq]; }                      \
        int gm0 = m0 + a_r;                                                      \
        avA = (gm0 < M) ? *(const float4*)&A[(long)gm0 * lda + (k0) + a_kq]      \
                        : make_float4(0.f, 0.f, 0.f, 0.f);                       \
        int gm1 = m0 + a_r + 64;                                                 \
        avB = (gm1 < M) ? *(const float4*)&A[(long)gm1 * lda + (k0) + a_kq]      \
                        : make_float4(0.f, 0.f, 0.f, 0.f);                       \
        if (tS) {                                                                \
            avA.x = fmaxf(fmaf(avA.x, ts0.x, th0.x), 0.f);                       \
            avA.y = fmaxf(fmaf(avA.y, ts0.y, th0.y), 0.f);                       \
            avA.z = fmaxf(fmaf(avA.z, ts0.z, th0.z), 0.f);                       \
            avA.w = fmaxf(fmaf(avA.w, ts0.w, th0.w), 0.f);                       \
            avB.x = fmaxf(fmaf(avB.x, ts0.x, th0.x), 0.f);                       \
            avB.y = fmaxf(fmaf(avB.y, ts0.y, th0.y), 0.f);                       \
            avB.z = fmaxf(fmaf(avB.z, ts0.z, th0.z), 0.f);                       \
            avB.w = fmaxf(fmaf(avB.w, ts0.w, th0.w), 0.f);                       \
        }                                                                        \
        bv0 = *(const float4*)&B[(long)((k0) + b_k) * ldb + n0 + b_n4];          \
        bv1 = *(const float4*)&B[(long)((k0) + b_k + 8) * ldb + n0 + b_n4];      \
    }

#define STS_STAGE(buf)                                                           \
    {                                                                            \
        As[buf][a_kq + 0][a_r] = avA.x;  As[buf][a_kq + 1][a_r] = avA.y;         \
        As[buf][a_kq + 2][a_r] = avA.z;  As[buf][a_kq + 3][a_r] = avA.w;         \
        As[buf][a_kq + 0][a_r + 64] = avB.x; As[buf][a_kq + 1][a_r + 64] = avB.y;\
        As[buf][a_kq + 2][a_r + 64] = avB.z; As[buf][a_kq + 3][a_r + 64] = avB.w;\
        {                                                                        \
            int off0 = b_n4 * 8;        int so0 = off0 ^ ((off0 >> 3) & 0x70);   \
            int off1 = b_n4 * 8 + 16;   int so1 = off1 ^ ((off1 >> 3) & 0x70);   \
            char* row0 = (char*)&Bs[buf][b_k][0];                                \
            char* row1 = (char*)&Bs[buf][b_k + 8][0];                            \
            *(float4*)(row0 + so0) = make_float4(bv0.x, bv0.x, bv0.y, bv0.y);    \
            *(float4*)(row0 + so1) = make_float4(bv0.z, bv0.z, bv0.w, bv0.w);    \
            *(float4*)(row1 + so0) = make_float4(bv1.x, bv1.x, bv1.y, bv1.y);    \
            *(float4*)(row1 + so1) = make_float4(bv1.z, bv1.z, bv1.w, bv1.w);    \
        }                                                                        \
    }

    LDG_STAGE(0);
    STS_STAGE(0);
    __syncthreads();

    int buf = 0;
    for (int k0 = 0; k0 < K; k0 += BK) {
        const bool has_next = (k0 + BK) < K;
        if (has_next) LDG_STAGE(k0 + BK);

#pragma unroll
        for (int kk = 0; kk < BK; kk++) {
            const float* ar = &As[buf][kk][0];
            ull a0, a1, a2, a3;
            {
                ulonglong2 t0 = *(const ulonglong2*)(ar + ty * 8);
                ulonglong2 t1 = *(const ulonglong2*)(ar + ty * 8 + 4);
                a0 = t0.x; a1 = t0.y; a2 = t1.x; a3 = t1.y;
            }
            ull bp[8];
            const char* br = (const char*)&Bs[buf][kk][0];
#pragma unroll
            for (int s = 0; s < 4; s++) {
                int off = tx * 64 + s * 16;
                off ^= (off >> 3) & 0x70;
                ulonglong2 tq = *(const ulonglong2*)(br + off);
                bp[2 * s] = tq.x; bp[2 * s + 1] = tq.y;
            }
#pragma unroll
            for (int j = 0; j < 8; j++) {
                acc[0][j] = fma2(a0, bp[j], acc[0][j]);
                acc[1][j] = fma2(a1, bp[j], acc[1][j]);
                acc[2][j] = fma2(a2, bp[j], acc[2][j]);
                acc[3][j] = fma2(a3, bp[j], acc[3][j]);
            }
        }

        if (has_next) STS_STAGE(buf ^ 1);
        __syncthreads();
        buf ^= 1;
    }

    // ---- epilogue: bias (+relu), packed rows (m, m+1) per acc pair ----
    float bb[8];
    {
        float4 c0 = *(const float4*)&biasp[n0 + tx * 8];
        float4 c1 = *(const float4*)&biasp[n0 + tx * 8 + 4];
        bb[0] = c0.x; bb[1] = c0.y; bb[2] = c0.z; bb[3] = c0.w;
        bb[4] = c1.x; bb[5] = c1.y; bb[6] = c1.z; bb[7] = c1.w;
    }
#pragma unroll
    for (int mp = 0; mp < 4; mp++) {
        int gm = m0 + ty * 8 + 2 * mp;
        float r0[8], r1[8];
#pragma unroll
        for (int j = 0; j < 8; j++) {
            float2 f = up2(acc[mp][j]);
            float v0 = f.x + bb[j];
            float v1 = f.y + bb[j];
            if (reluEpi) { v0 = fmaxf(v0, 0.f); v1 = fmaxf(v1, 0.f); }
            r0[j] = v0; r1[j] = v1;
        }
        if (gm < M) {
            float4* p = (float4*)&C[(long)gm * ldc + n0 + tx * 8];
            p[0] = make_float4(r0[0], r0[1], r0[2], r0[3]);
            p[1] = make_float4(r0[4], r0[5], r0[6], r0[7]);
        }
        if (gm + 1 < M) {
            float4* p = (float4*)&C[(long)(gm + 1) * ldc + n0 + tx * 8];
            p[0] = make_float4(r1[0], r1[1], r1[2], r1[3]);
            p[1] = make_float4(r1[4], r1[5], r1[6], r1[7]);
        }
    }
#undef LDG_STAGE
#undef STS_STAGE
}

// ---------------- BN statistics ----------------
__global__ void zero_stats_kernel(double* a, double* b, int n)
{
    int i = blockIdx.x * blockDim.x + threadIdx.x;
    if (i < n) { a[i] = 0.0; b[i] = 0.0; }
}

__global__ void stats_kernel(const float* __restrict__ X, long xBatch, int ld, int M,
                             double* __restrict__ sum, double* __restrict__ sq,
                             int sBatch, int rowsPer)
{
    const int col = blockIdx.y * 256 + threadIdx.x;
    const float* Xb = X + (long)blockIdx.z * xBatch;
    int r0 = blockIdx.x * rowsPer;
    int r1 = min(r0 + rowsPer, M);
    double s = 0.0, q = 0.0;
    for (int r = r0; r < r1; r++) {
        float v = __ldg(&Xb[(long)r * ld + col]);
        s += v;
        q += (double)v * (double)v;
    }
    atomicAdd(&sum[blockIdx.z * sBatch + col], s);
    atomicAdd(&sq [blockIdx.z * sBatch + col], q);
}

__global__ void finalize_bn_kernel(const double* __restrict__ sum, const double* __restrict__ sq,
                                   const float* __restrict__ g, const float* __restrict__ be,
                                   float* __restrict__ sc, float* __restrict__ sh,
                                   int n, float invN)
{
    int i = blockIdx.x * blockDim.x + threadIdx.x;
    if (i >= n) return;
    float mu  = (float)(sum[i] * (double)invN);
    float var = (float)(sq[i] * (double)invN) - mu * mu;
    float s = g[i] * rsqrtf(var + EPSBN);
    sc[i] = s;
    sh[i] = be[i] - mu * s;
}

// ---------------- KAN ----------------
// Uniform grid: g[j] = (j-3)*0.4 - 1, j = 0..11 ; spline order 3 -> 8 final bases
__device__ __forceinline__ void bspline8(float x, float bs[11])
{
#pragma unroll
    for (int j = 0; j < 11; j++) {
        float gl = (float)(j - 3) * 0.4f - 1.0f;
        float gr = (float)(j - 2) * 0.4f - 1.0f;
        bs[j] = (x >= gl && x < gr) ? 1.0f : 0.0f;
    }
#pragma unroll
    for (int p = 1; p <= 3; p++) {
        float inv = 1.0f / (0.4f * (float)p);
#pragma unroll
        for (int j = 0; j < 11 - p; j++) {
            float gj   = (float)(j - 3) * 0.4f - 1.0f;       // g[j]
            float gjp1 = (float)(j + p - 2) * 0.4f - 1.0f;   // g[j+p+1]
            bs[j] = ((x - gj) * bs[j] + (gjp1 - x) * bs[j + 1]) * inv;
        }
    }
}

template <int IN, int OUTC>
__global__ void __launch_bounds__(128)
kan_kernel(const float* __restrict__ X, const float* __restrict__ bw,
           const float* __restrict__ sw, const float* __restrict__ sc,
           float* __restrict__ out, int n)
{
    int node = blockIdx.x * blockDim.x + threadIdx.x;
    if (node >= n) return;
    float acc[OUTC];
#pragma unroll
    for (int o = 0; o < OUTC; o++) acc[o] = 0.f;

    for (int i = 0; i < IN; i++) {
        float x = __ldg(&X[(long)node * IN + i]);
        float bs[11];
        bspline8(x, bs);
        float s = x / (1.0f + expf(-x));   // silu
#pragma unroll 4
        for (int o = 0; o < OUTC; o++) {
            const float4* swp = (const float4*)(sw + ((long)o * IN + i) * 8);
            float4 w0 = __ldg(&swp[0]);
            float4 w1 = __ldg(&swp[1]);
            float sp = bs[0] * w0.x + bs[1] * w0.y + bs[2] * w0.z + bs[3] * w0.w
                     + bs[4] * w1.x + bs[5] * w1.y + bs[6] * w1.z + bs[7] * w1.w;
            acc[o] = fmaf(s, __ldg(&bw[(long)o * IN + i]),
                     fmaf(sp, __ldg(&sc[(long)o * IN + i]), acc[o]));
        }
    }
#pragma unroll
    for (int o = 0; o < OUTC; o++) out[(long)node * OUTC + o] = acc[o];
}

// ---------------- launch ----------------
extern "C" void kernel_launch(void* const* d_in, const int* in_sizes, int n_in,
                              void* d_out, int out_size)
{
    const float* x   = (const float*)d_in[0];
    // d_in[1] edge_index, d_in[2] edge_attr : unused (ChebConv K=1)
    const float* W1  = (const float*)d_in[3];
    const float* b1  = (const float*)d_in[4];
    const float* gm1 = (const float*)d_in[5];
    const float* bt1 = (const float*)d_in[6];
    const float* W2  = (const float*)d_in[7];
    const float* b2  = (const float*)d_in[8];
    const float* gm2 = (const float*)d_in[9];
    const float* bt2 = (const float*)d_in[10];
    const float* Wf  = (const float*)d_in[11];
    const float* bf  = (const float*)d_in[12];
    const float* bw1 = (const float*)d_in[13];
    const float* sw1 = (const float*)d_in[14];
    const float* sc1 = (const float*)d_in[15];
    const float* bw2 = (const float*)d_in[16];
    const float* sw2 = (const float*)d_in[17];
    const float* sc2 = (const float*)d_in[18];

    float  *h1, *hc, *f, *f2;
    double *s1, *q1, *s2, *q2;
    float  *sca1, *shf1, *sca2, *shf2;
    cudaGetSymbolAddress((void**)&h1,  g_h1);
    cudaGetSymbolAddress((void**)&hc,  g_hc);
    cudaGetSymbolAddress((void**)&f,   g_f);
    cudaGetSymbolAddress((void**)&f2,  g_f2);
    cudaGetSymbolAddress((void**)&s1,  g_sum1);
    cudaGetSymbolAddress((void**)&q1,  g_sq1);
    cudaGetSymbolAddress((void**)&s2,  g_sum2);
    cudaGetSymbolAddress((void**)&q2,  g_sq2);
    cudaGetSymbolAddress((void**)&sca1, g_scale1);
    cudaGetSymbolAddress((void**)&shf1, g_shift1);
    cudaGetSymbolAddress((void**)&sca2, g_scale2);
    cudaGetSymbolAddress((void**)&shf2, g_shift2);

    const int mBlocks = (NNODE + BM - 1) / BM;   // 157

    // 1) h1 = x @ W1 + b1   (per-branch)
    {
        dim3 grid(HDIM / BN, mBlocks, BATCH);
        sgemm2_kernel<<<grid, GEMM_THREADS>>>(x, (long)NNODE * FEATD, FEATD,
                                              W1, (long)FEATD * HDIM, HDIM,
                                              b1, HDIM,
                                              h1, (long)NNODE * HDIM, HDIM,
                                              nullptr, nullptr, 0,
                                              NNODE, HDIM, FEATD, 0);
    }

    // 2) BN1 stats -> scale/shift (per branch*channel)
    zero_stats_kernel<<<(HCW + 255) / 256, 256>>>(s1, q1, HCW);
    {
        dim3 grid((NNODE + 255) / 256, HDIM / 256, BATCH);
        stats_kernel<<<grid, 256>>>(h1, (long)NNODE * HDIM, HDIM, NNODE, s1, q1, HDIM, 256);
    }
    finalize_bn_kernel<<<(HCW + 255) / 256, 256>>>(s1, q1, gm1, bt1, sca1, shf1, HCW, 1.0f / NNODE);

    // 3) hc[:, b*512:(b+1)*512] = relu(BN1(h1_b)) @ W2_b + b2_b
    {
        dim3 grid(HDIM / BN, mBlocks, BATCH);
        sgemm2_kernel<<<grid, GEMM_THREADS>>>(h1, (long)NNODE * HDIM, HDIM,
                                              W2, (long)HDIM * HDIM, HDIM,
                                              b2, HDIM,
                                              hc, (long)HDIM /*column offset b*512*/, HCW,
                                              sca1, shf1, HDIM,
                                              NNODE, HDIM, HDIM, 0);
    }

    // 4) BN2 stats over hc columns
    zero_stats_kernel<<<(HCW + 255) / 256, 256>>>(s2, q2, HCW);
    {
        dim3 grid((NNODE + 255) / 256, HCW / 256, 1);
        stats_kernel<<<grid, 256>>>(hc, 0, HCW, NNODE, s2, q2, 0, 256);
    }
    finalize_bn_kernel<<<(HCW + 255) / 256, 256>>>(s2, q2, gm2, bt2, sca2, shf2, HCW, 1.0f / NNODE);

    // 5) f = relu( relu(BN2(hc)) @ Wf + bf )
    {
        dim3 grid(F1D / BN, mBlocks, 1);
        sgemm2_kernel<<<grid, GEMM_THREADS>>>(hc, 0, HCW,
                                              Wf, 0, F1D,
                                              bf, 0,
                                              f, 0, F1D,
                                              sca2, shf2, 0,
                                              NNODE, F1D, HCW, 1);
    }

    // 6) KAN 1024 -> 32
    kan_kernel<F1D, KO1><<<(NNODE + 127) / 128, 128>>>(f, bw1, sw1, sc1, f2, NNODE);

    // 7) KAN 32 -> 10 -> d_out
    kan_kernel<KO1, KO2><<<(NNODE + 127) / 128, 128>>>(f2, bw2, sw2, sc2, (float*)d_out, NNODE);
}

// round 5
// speedup vs baseline: 1.5483x; 1.5483x over previous
#include <cuda_runtime.h>
#include <cuda_bf16.h>
#include <math.h>
#include <stdint.h>

#define BATCH 8
#define NNODE 20000
#define FEATD 256
#define HDIM  512
#define HCW   4096
#define F1D   1024
#define KO1   32
#define KO2   10
#define EPSBN 1e-5f
#define SROWS 64

typedef __nv_bfloat16 bf16;

// ---------------- scratch ----------------
__device__ __align__(16) float g_h1[(size_t)BATCH * NNODE * HDIM];
__device__ __align__(16) float g_hc[(size_t)NNODE * HCW];
__device__ __align__(16) float g_f [(size_t)NNODE * F1D];
__device__ __align__(16) float g_f2[(size_t)NNODE * KO1];

__device__ __align__(16) bf16 g_xhi[(size_t)BATCH * NNODE * FEATD];
__device__ __align__(16) bf16 g_xlo[(size_t)BATCH * NNODE * FEATD];
__device__ __align__(16) bf16 g_h1hi[(size_t)BATCH * NNODE * HDIM];
__device__ __align__(16) bf16 g_h1lo[(size_t)BATCH * NNODE * HDIM];
__device__ __align__(16) bf16 g_hchi[(size_t)NNODE * HCW];
__device__ __align__(16) bf16 g_hclo[(size_t)NNODE * HCW];
__device__ __align__(16) bf16 g_w1hi[(size_t)BATCH * HDIM * FEATD];
__device__ __align__(16) bf16 g_w1lo[(size_t)BATCH * HDIM * FEATD];
__device__ __align__(16) bf16 g_w2hi[(size_t)BATCH * HDIM * HDIM];
__device__ __align__(16) bf16 g_w2lo[(size_t)BATCH * HDIM * HDIM];
__device__ __align__(16) bf16 g_wfhi[(size_t)F1D * HCW];
__device__ __align__(16) bf16 g_wflo[(size_t)F1D * HCW];

__device__ float2 g_part[SROWS * HCW];
__device__ float  g_scale1[HCW], g_shift1[HCW];
__device__ float  g_scale2[HCW], g_shift2[HCW];

// ================= PTX helpers (all compute_80-era, compute_103-safe) =================
__device__ __forceinline__ uint32_t smem_u32(const void* p) {
    uint32_t a;
    asm("{ .reg .u64 t; cvta.to.shared.u64 t, %1; cvt.u32.u64 %0, t; }" : "=r"(a) : "l"(p));
    return a;
}
__device__ __forceinline__ void cpa16(uint32_t dst, const void* src, bool pred) {
    int sz = pred ? 16 : 0;
    asm volatile("cp.async.cg.shared.global [%0], [%1], 16, %2;" :: "r"(dst), "l"(src), "r"(sz) : "memory");
}
__device__ __forceinline__ void cpa_commit() { asm volatile("cp.async.commit_group;" ::: "memory"); }
__device__ __forceinline__ void cpa_wait1() { asm volatile("cp.async.wait_group 1;" ::: "memory"); }
__device__ __forceinline__ void cpa_wait0() { asm volatile("cp.async.wait_group 0;" ::: "memory"); }

__device__ __forceinline__ void ldsm_x4(uint32_t& r0, uint32_t& r1, uint32_t& r2, uint32_t& r3, uint32_t addr) {
    asm volatile("ldmatrix.sync.aligned.m8n8.x4.shared.b16 {%0,%1,%2,%3}, [%4];"
                 : "=r"(r0), "=r"(r1), "=r"(r2), "=r"(r3) : "r"(addr));
}
__device__ __forceinline__ void mma16816(float* c, uint32_t a0, uint32_t a1, uint32_t a2, uint32_t a3,
                                         uint32_t b0, uint32_t b1) {
    asm volatile("mma.sync.aligned.m16n8k16.row.col.f32.bf16.bf16.f32 "
                 "{%0,%1,%2,%3}, {%4,%5,%6,%7}, {%8,%9}, {%0,%1,%2,%3};"
                 : "+f"(c[0]), "+f"(c[1]), "+f"(c[2]), "+f"(c[3])
                 : "r"(a0), "r"(a1), "r"(a2), "r"(a3), "r"(b0), "r"(b1));
}
static __device__ __forceinline__ uint32_t sw128(uint32_t off) { return off ^ ((off >> 3) & 0x70); }

// ================= HMMA GEMM (bf16 3-product split, fp32 accum) =================
// C[M x N] = epi( A * B^T + bias ), A[m][k] hi/lo, B[n][k] hi/lo. N tile 128, K % 64 == 0.
#define GTHREADS 256
#define KC 64
#define STAGE_BYTES 65536          // 4 arrays x 16KB (128 rows x 128B)
#define GEMM_SMEM (2 * STAGE_BYTES + 1024)

__global__ void __launch_bounds__(GTHREADS)
gemm_mma_kernel(const bf16* __restrict__ Ahi, const bf16* __restrict__ Alo, long aBatch,
                const bf16* __restrict__ Bhi, const bf16* __restrict__ Blo, long bBatch,
                const float* __restrict__ bias, long biasBatch,
                float* __restrict__ C, long cBatch, int ldc,
                int M, int K, int reluEpi)
{
    extern __shared__ char smem[];
    const uint32_t S = (smem_u32(smem) + 1023) & ~1023u;

    const int bz = blockIdx.z;
    Ahi += (long)bz * aBatch;  Alo += (long)bz * aBatch;
    Bhi += (long)bz * bBatch;  Blo += (long)bz * bBatch;
    const float* bp = bias + (long)bz * biasBatch;
    C += (long)bz * cBatch;

    const int n0 = blockIdx.x * 128;
    const int m0 = blockIdx.y * 128;
    const int t  = threadIdx.x;
    const int wid = t >> 5, lid = t & 31;
    const int warp_m = wid & 3;          // 4 warps in m (32 rows each)
    const int warp_n = wid >> 2;         // 2 warps in n (64 cols each)
    const int T = K / KC;

    // ---- stage loader: 4 arrays of 128 rows x 128B, SW128 ----
    auto load_tile = [&](int kt, int stg) {
        const uint32_t sb = S + stg * STAGE_BYTES;
        const int kbase = kt * KC;
#pragma unroll
        for (int j = 0; j < 4; j++) {
            int cid = t + j * 256;                 // 0..1023
            int row = cid >> 3, c16 = cid & 7;
            uint32_t dsw = sw128((uint32_t)(row * 128 + c16 * 16));
            size_t aoff = (size_t)(m0 + row) * K + kbase + c16 * 8;
            bool ap = (m0 + row) < M;
            cpa16(sb + dsw,          Ahi + aoff, ap);
            cpa16(sb + 16384 + dsw,  Alo + aoff, ap);
            size_t boff = (size_t)(n0 + row) * K + kbase + c16 * 8;
            cpa16(sb + 32768 + dsw,  Bhi + boff, true);
            cpa16(sb + 49152 + dsw,  Blo + boff, true);
        }
        cpa_commit();
    };

    float acc[2][8][4];
#pragma unroll
    for (int i = 0; i < 2; i++)
#pragma unroll
        for (int j = 0; j < 8; j++)
#pragma unroll
            for (int q = 0; q < 4; q++) acc[i][j][q] = 0.f;

    load_tile(0, 0);
    if (T > 1) load_tile(1, 1); else cpa_commit();

    const int lrow = lid & 15;
    const int lhalf = (lid >> 4) * 16;

    for (int kt = 0; kt < T; kt++) {
        cpa_wait1();
        __syncthreads();
        const uint32_t sb = S + (kt & 1) * STAGE_BYTES;

#pragma unroll
        for (int kk = 0; kk < 4; kk++) {
            const int kb = kk * 32;
            uint32_t ah[2][4], al[2][4];
#pragma unroll
            for (int mf = 0; mf < 2; mf++) {
                int row = warp_m * 32 + mf * 16 + lrow;
                uint32_t off = sw128((uint32_t)(row * 128 + kb + lhalf));
                ldsm_x4(ah[mf][0], ah[mf][1], ah[mf][2], ah[mf][3], sb + off);
                ldsm_x4(al[mf][0], al[mf][1], al[mf][2], al[mf][3], sb + 16384 + off);
            }
            uint32_t bh[4][4], bl[4][4];
#pragma unroll
            for (int g = 0; g < 4; g++) {
                int row = warp_n * 64 + g * 16 + lrow;
                uint32_t off = sw128((uint32_t)(row * 128 + kb + lhalf));
                ldsm_x4(bh[g][0], bh[g][1], bh[g][2], bh[g][3], sb + 32768 + off);
                ldsm_x4(bl[g][0], bl[g][1], bl[g][2], bl[g][3], sb + 49152 + off);
            }
#pragma unroll
            for (int mf = 0; mf < 2; mf++)
#pragma unroll
                for (int nf = 0; nf < 8; nf++) {
                    int g = nf >> 1, od = nf & 1;
                    uint32_t bh0 = od ? bh[g][1] : bh[g][0];
                    uint32_t bh1 = od ? bh[g][3] : bh[g][2];
                    uint32_t bl0 = od ? bl[g][1] : bl[g][0];
                    uint32_t bl1 = od ? bl[g][3] : bl[g][2];
                    mma16816(acc[mf][nf], ah[mf][0], ah[mf][1], ah[mf][2], ah[mf][3], bh0, bh1);
                    mma16816(acc[mf][nf], ah[mf][0], ah[mf][1], ah[mf][2], ah[mf][3], bl0, bl1);
                    mma16816(acc[mf][nf], al[mf][0], al[mf][1], al[mf][2], al[mf][3], bh0, bh1);
                }
        }
        __syncthreads();
        if (kt + 2 < T) load_tile(kt + 2, kt & 1); else cpa_commit();
    }
    cpa_wait0();

    // ---- epilogue ----
#pragma unroll
    for (int mf = 0; mf < 2; mf++) {
        int rbase = m0 + warp_m * 32 + mf * 16 + (lid >> 2);
#pragma unroll
        for (int nf = 0; nf < 8; nf++) {
            int col = n0 + warp_n * 64 + nf * 8 + (lid & 3) * 2;
            float bx = __ldg(&bp[col]), by = __ldg(&bp[col + 1]);
            float v0 = acc[mf][nf][0] + bx, v1 = acc[mf][nf][1] + by;
            float v2 = acc[mf][nf][2] + bx, v3 = acc[mf][nf][3] + by;
            if (reluEpi) {
                v0 = fmaxf(v0, 0.f); v1 = fmaxf(v1, 0.f);
                v2 = fmaxf(v2, 0.f); v3 = fmaxf(v3, 0.f);
            }
            if (rbase < M)     *(float2*)&C[(size_t)rbase * ldc + col]       = make_float2(v0, v1);
            if (rbase + 8 < M) *(float2*)&C[(size_t)(rbase + 8) * ldc + col] = make_float2(v2, v3);
        }
    }
}

// ================= split / transpose kernels =================
__global__ void split_kernel(const float* __restrict__ in, bf16* __restrict__ hi,
                             bf16* __restrict__ lo, size_t n)
{
    size_t i = ((size_t)blockIdx.x * blockDim.x + threadIdx.x) * 4;
    if (i >= n) return;
    float4 v = *(const float4*)(in + i);
    bf16 h0 = __float2bfloat16(v.x), h1 = __float2bfloat16(v.y);
    bf16 h2 = __float2bfloat16(v.z), h3 = __float2bfloat16(v.w);
    hi[i] = h0; hi[i+1] = h1; hi[i+2] = h2; hi[i+3] = h3;
    lo[i]   = __float2bfloat16(v.x - __bfloat162float(h0));
    lo[i+1] = __float2bfloat16(v.y - __bfloat162float(h1));
    lo[i+2] = __float2bfloat16(v.z - __bfloat162float(h2));
    lo[i+3] = __float2bfloat16(v.w - __bfloat162float(h3));
}

__global__ void split_affine_kernel(const float* __restrict__ in,
                                    const float* __restrict__ sc, const float* __restrict__ sh,
                                    int ld, bf16* __restrict__ hi, bf16* __restrict__ lo, size_t n)
{
    size_t i = ((size_t)blockIdx.x * blockDim.x + threadIdx.x) * 4;
    if (i >= n) return;
    float4 v = *(const float4*)(in + i);
    int col = (int)(i % ld);
    int soff = (int)(i / ((size_t)ld * NNODE)) * ld + col;
    float4 s = *(const float4*)(sc + soff);
    float4 h = *(const float4*)(sh + soff);
    float w0 = fmaxf(fmaf(v.x, s.x, h.x), 0.f);
    float w1 = fmaxf(fmaf(v.y, s.y, h.y), 0.f);
    float w2 = fmaxf(fmaf(v.z, s.z, h.z), 0.f);
    float w3 = fmaxf(fmaf(v.w, s.w, h.w), 0.f);
    bf16 a0 = __float2bfloat16(w0), a1 = __float2bfloat16(w1);
    bf16 a2 = __float2bfloat16(w2), a3 = __float2bfloat16(w3);
    hi[i] = a0; hi[i+1] = a1; hi[i+2] = a2; hi[i+3] = a3;
    lo[i]   = __float2bfloat16(w0 - __bfloat162float(a0));
    lo[i+1] = __float2bfloat16(w1 - __bfloat162float(a1));
    lo[i+2] = __float2bfloat16(w2 - __bfloat162float(a2));
    lo[i+3] = __float2bfloat16(w3 - __bfloat162float(a3));
}

__global__ void tsplit_kernel(const float* __restrict__ W, long wBatch, int K, int Nn,
                              bf16* __restrict__ hi, bf16* __restrict__ lo, long oBatch)
{
    __shared__ float tile[32][33];
    const float* Wb = W + (long)blockIdx.z * wBatch;
    bf16* hib = hi + (long)blockIdx.z * oBatch;
    bf16* lob = lo + (long)blockIdx.z * oBatch;
    int nb = blockIdx.x * 32, kb = blockIdx.y * 32;
    int tx = threadIdx.x, ty = threadIdx.y;
#pragma unroll
    for (int r = 0; r < 32; r += 8)
        tile[ty + r][tx] = Wb[(size_t)(kb + ty + r) * Nn + nb + tx];
    __syncthreads();
#pragma unroll
    for (int r = 0; r < 32; r += 8) {
        float v = tile[tx][ty + r];
        bf16 h = __float2bfloat16(v);
        size_t o = (size_t)(nb + ty + r) * K + kb + tx;
        hib[o] = h;
        lob[o] = __float2bfloat16(v - __bfloat162float(h));
    }
}

// ================= BN statistics (deterministic two-phase) =================
__global__ void stats_part_kernel(const float* __restrict__ X, long xBatch, int ld, int M,
                                  float2* __restrict__ part)
{
    const int col = blockIdx.y * 256 + threadIdx.x;
    const float* Xb = X + (long)blockIdx.z * xBatch;
    const int rowsPer = (M + SROWS - 1) / SROWS;
    int r0 = blockIdx.x * rowsPer;
    int r1 = min(r0 + rowsPer, M);
    float s = 0.f, q = 0.f;
    for (int r = r0; r < r1; r++) {
        float v = __ldg(&Xb[(size_t)r * ld + col]);
        s += v; q = fmaf(v, v, q);
    }
    part[(size_t)blockIdx.x * HCW + blockIdx.z * ld + col] = make_float2(s, q);
}

__global__ void finalize_bn_kernel(const float2* __restrict__ part,
                                   const float* __restrict__ g, const float* __restrict__ be,
                                   float* __restrict__ sc, float* __restrict__ sh, float invN)
{
    int i = blockIdx.x * blockDim.x + threadIdx.x;
    float s = 0.f, q = 0.f;
#pragma unroll 8
    for (int r = 0; r < SROWS; r++) {
        float2 p = part[(size_t)r * HCW + i];
        s += p.x; q += p.y;
    }
    float mu  = s * invN;
    float var = q * invN - mu * mu;
    float sl = g[i] * rsqrtf(var + EPSBN);
    sc[i] = sl;
    sh[i] = be[i] - mu * sl;
}

// ================= KAN =================
__device__ __forceinline__ void bspline8(float x, float bs[11])
{
#pragma unroll
    for (int j = 0; j < 11; j++) {
        float gl = (float)(j - 3) * 0.4f - 1.0f;
        float gr = (float)(j - 2) * 0.4f - 1.0f;
        bs[j] = (x >= gl && x < gr) ? 1.0f : 0.0f;
    }
#pragma unroll
    for (int p = 1; p <= 3; p++) {
        float inv = 1.0f / (0.4f * (float)p);
#pragma unroll
        for (int j = 0; j < 11 - p; j++) {
            float gj   = (float)(j - 3) * 0.4f - 1.0f;
            float gjp1 = (float)(j + p - 2) * 0.4f - 1.0f;
            bs[j] = ((x - gj) * bs[j] + (gjp1 - x) * bs[j + 1]) * inv;
        }
    }
}

template <int IN, int OUTC>
__global__ void __launch_bounds__(128)
kan_kernel(const float* __restrict__ X, const float* __restrict__ bw,
           const float* __restrict__ sw, const float* __restrict__ sc,
           float* __restrict__ out, int n)
{
    int node = blockIdx.x * blockDim.x + threadIdx.x;
    if (node >= n) return;
    float acc[OUTC];
#pragma unroll
    for (int o = 0; o < OUTC; o++) acc[o] = 0.f;

    for (int i = 0; i < IN; i++) {
        float x = __ldg(&X[(size_t)node * IN + i]);
        float bs[11];
        bspline8(x, bs);
        float s = x / (1.0f + expf(-x));
#pragma unroll 4
        for (int o = 0; o < OUTC; o++) {
            const float4* swp = (const float4*)(sw + ((size_t)o * IN + i) * 8);
            float4 w0 = __ldg(&swp[0]);
            float4 w1 = __ldg(&swp[1]);
            float sp = bs[0] * w0.x + bs[1] * w0.y + bs[2] * w0.z + bs[3] * w0.w
                     + bs[4] * w1.x + bs[5] * w1.y + bs[6] * w1.z + bs[7] * w1.w;
            acc[o] = fmaf(s, __ldg(&bw[(size_t)o * IN + i]),
                     fmaf(sp, __ldg(&sc[(size_t)o * IN + i]), acc[o]));
        }
    }
#pragma unroll
    for (int o = 0; o < OUTC; o++) out[(size_t)node * OUTC + o] = acc[o];
}

// ================= launch =================
extern "C" void kernel_launch(void* const* d_in, const int* in_sizes, int n_in,
                              void* d_out, int out_size)
{
    const float* x   = (const float*)d_in[0];
    const float* W1  = (const float*)d_in[3];
    const float* b1  = (const float*)d_in[4];
    const float* gm1 = (const float*)d_in[5];
    const float* bt1 = (const float*)d_in[6];
    const float* W2  = (const float*)d_in[7];
    const float* b2  = (const float*)d_in[8];
    const float* gm2 = (const float*)d_in[9];
    const float* bt2 = (const float*)d_in[10];
    const float* Wf  = (const float*)d_in[11];
    const float* bf  = (const float*)d_in[12];
    const float* bw1 = (const float*)d_in[13];
    const float* sw1 = (const float*)d_in[14];
    const float* sc1 = (const float*)d_in[15];
    const float* bw2 = (const float*)d_in[16];
    const float* sw2 = (const float*)d_in[17];
    const float* sc2 = (const float*)d_in[18];

    float *h1, *hc, *f, *f2, *sca1, *shf1, *sca2, *shf2;
    float2 *part;
    bf16 *xhi, *xlo, *h1hi, *h1lo, *hchi, *hclo, *w1hi, *w1lo, *w2hi, *w2lo, *wfhi, *wflo;
    cudaGetSymbolAddress((void**)&h1, g_h1);   cudaGetSymbolAddress((void**)&hc, g_hc);
    cudaGetSymbolAddress((void**)&f, g_f);     cudaGetSymbolAddress((void**)&f2, g_f2);
    cudaGetSymbolAddress((void**)&xhi, g_xhi); cudaGetSymbolAddress((void**)&xlo, g_xlo);
    cudaGetSymbolAddress((void**)&h1hi, g_h1hi); cudaGetSymbolAddress((void**)&h1lo, g_h1lo);
    cudaGetSymbolAddress((void**)&hchi, g_hchi); cudaGetSymbolAddress((void**)&hclo, g_hclo);
    cudaGetSymbolAddress((void**)&w1hi, g_w1hi); cudaGetSymbolAddress((void**)&w1lo, g_w1lo);
    cudaGetSymbolAddress((void**)&w2hi, g_w2hi); cudaGetSymbolAddress((void**)&w2lo, g_w2lo);
    cudaGetSymbolAddress((void**)&wfhi, g_wfhi); cudaGetSymbolAddress((void**)&wflo, g_wflo);
    cudaGetSymbolAddress((void**)&part, g_part);
    cudaGetSymbolAddress((void**)&sca1, g_scale1); cudaGetSymbolAddress((void**)&shf1, g_shift1);
    cudaGetSymbolAddress((void**)&sca2, g_scale2); cudaGetSymbolAddress((void**)&shf2, g_shift2);

    cudaFuncSetAttribute(gemm_mma_kernel, cudaFuncAttributeMaxDynamicSharedMemorySize, GEMM_SMEM);

    const int mT = (NNODE + 127) / 128;   // 157
    dim3 tb(32, 8);

    // weight transpose+split (W [K x N] -> [N x K] hi/lo)
    tsplit_kernel<<<dim3(HDIM/32, FEATD/32, BATCH), tb>>>(W1, (long)FEATD*HDIM, FEATD, HDIM, w1hi, w1lo, (long)HDIM*FEATD);
    tsplit_kernel<<<dim3(HDIM/32, HDIM/32, BATCH), tb>>>(W2, (long)HDIM*HDIM, HDIM, HDIM, w2hi, w2lo, (long)HDIM*HDIM);
    tsplit_kernel<<<dim3(F1D/32, HCW/32, 1), tb>>>(Wf, 0, HCW, F1D, wfhi, wflo, 0);

    // x -> hi/lo
    {
        size_t n = (size_t)BATCH * NNODE * FEATD;
        split_kernel<<<(unsigned)((n/4 + 255)/256), 256>>>(x, xhi, xlo, n);
    }

    // GEMM1: h1 = x @ W1 + b1
    gemm_mma_kernel<<<dim3(HDIM/128, mT, BATCH), GTHREADS, GEMM_SMEM>>>(
        xhi, xlo, (long)NNODE*FEATD, w1hi, w1lo, (long)HDIM*FEATD,
        b1, HDIM, h1, (long)NNODE*HDIM, HDIM, NNODE, FEATD, 0);

    // BN1 stats + finalize
    stats_part_kernel<<<dim3(SROWS, HDIM/256, BATCH), 256>>>(h1, (long)NNODE*HDIM, HDIM, NNODE, part);
    finalize_bn_kernel<<<HCW/256, 256>>>(part, gm1, bt1, sca1, shf1, 1.0f/NNODE);

    // split h1 (affine+relu baked)
    {
        size_t n = (size_t)BATCH * NNODE * HDIM;
        split_affine_kernel<<<(unsigned)((n/4 + 255)/256), 256>>>(h1, sca1, shf1, HDIM, h1hi, h1lo, n);
    }

    // GEMM2: hc[:, b*512:(b+1)*512] = h1' @ W2 + b2
    gemm_mma_kernel<<<dim3(HDIM/128, mT, BATCH), GTHREADS, GEMM_SMEM>>>(
        h1hi, h1lo, (long)NNODE*HDIM, w2hi, w2lo, (long)HDIM*HDIM,
        b2, HDIM, hc, (long)HDIM /*col offset*/, HCW, NNODE, HDIM, 0);

    // BN2 stats + finalize
    stats_part_kernel<<<dim3(SROWS, HCW/256, 1), 256>>>(hc, 0, HCW, NNODE, part);
    finalize_bn_kernel<<<HCW/256, 256>>>(part, gm2, bt2, sca2, shf2, 1.0f/NNODE);

    // split hc
    {
        size_t n = (size_t)NNODE * HCW;
        split_affine_kernel<<<(unsigned)((n/4 + 255)/256), 256>>>(hc, sca2, shf2, HCW, hchi, hclo, n);
    }

    // GEMM3: f = relu(hc' @ Wf + bf)
    gemm_mma_kernel<<<dim3(F1D/128, mT, 1), GTHREADS, GEMM_SMEM>>>(
        hchi, hclo, 0, wfhi, wflo, 0,
        bf, 0, f, 0, F1D, NNODE, HCW, 1);

    // KAN
    kan_kernel<F1D, KO1><<<(NNODE + 127)/128, 128>>>(f, bw1, sw1, sc1, f2, NNODE);
    kan_kernel<KO1, KO2><<<(NNODE + 127)/128, 128>>>(f2, bw2, sw2, sc2, (float*)d_out, NNODE);
}

// round 6
// speedup vs baseline: 2.2341x; 1.4429x over previous
#include <cuda_runtime.h>
#include <cuda_bf16.h>
#include <math.h>
#include <stdint.h>

#define BATCH 8
#define NNODE 20000
#define FEATD 256
#define HDIM  512
#define HCW   4096
#define F1D   1024
#define KO1   32
#define KO2   10
#define EPSBN 1e-5f
#define SROWS 64

typedef __nv_bfloat16 bf16;

// ---------------- scratch ----------------
__device__ __align__(16) float g_h1[(size_t)BATCH * NNODE * HDIM];
__device__ __align__(16) float g_hc[(size_t)NNODE * HCW];
__device__ __align__(16) float g_f [(size_t)NNODE * F1D];
__device__ __align__(16) float g_f2[(size_t)NNODE * KO1];

__device__ __align__(16) bf16 g_xhi[(size_t)BATCH * NNODE * FEATD];
__device__ __align__(16) bf16 g_xlo[(size_t)BATCH * NNODE * FEATD];
__device__ __align__(16) bf16 g_h1hi[(size_t)BATCH * NNODE * HDIM];
__device__ __align__(16) bf16 g_h1lo[(size_t)BATCH * NNODE * HDIM];
__device__ __align__(16) bf16 g_hchi[(size_t)NNODE * HCW];
__device__ __align__(16) bf16 g_hclo[(size_t)NNODE * HCW];
__device__ __align__(16) bf16 g_w1hi[(size_t)BATCH * HDIM * FEATD];
__device__ __align__(16) bf16 g_w1lo[(size_t)BATCH * HDIM * FEATD];
__device__ __align__(16) bf16 g_w2hi[(size_t)BATCH * HDIM * HDIM];
__device__ __align__(16) bf16 g_w2lo[(size_t)BATCH * HDIM * HDIM];
__device__ __align__(16) bf16 g_wfhi[(size_t)F1D * HCW];
__device__ __align__(16) bf16 g_wflo[(size_t)F1D * HCW];

__device__ float2 g_part[SROWS * HCW];
__device__ float  g_scale1[HCW], g_shift1[HCW];
__device__ float  g_scale2[HCW], g_shift2[HCW];

// ================= PTX helpers (compute_103-safe) =================
__device__ __forceinline__ uint32_t smem_u32(const void* p) {
    uint32_t a;
    asm("{ .reg .u64 t; cvta.to.shared.u64 t, %1; cvt.u32.u64 %0, t; }" : "=r"(a) : "l"(p));
    return a;
}
__device__ __forceinline__ void cpa16(uint32_t dst, const void* src, bool pred) {
    int sz = pred ? 16 : 0;
    asm volatile("cp.async.cg.shared.global [%0], [%1], 16, %2;" :: "r"(dst), "l"(src), "r"(sz) : "memory");
}
__device__ __forceinline__ void cpa_commit() { asm volatile("cp.async.commit_group;" ::: "memory"); }
__device__ __forceinline__ void cpa_wait2() { asm volatile("cp.async.wait_group 2;" ::: "memory"); }
__device__ __forceinline__ void cpa_wait0() { asm volatile("cp.async.wait_group 0;" ::: "memory"); }

__device__ __forceinline__ void ldsm_x4(uint32_t& r0, uint32_t& r1, uint32_t& r2, uint32_t& r3, uint32_t addr) {
    asm volatile("ldmatrix.sync.aligned.m8n8.x4.shared.b16 {%0,%1,%2,%3}, [%4];"
                 : "=r"(r0), "=r"(r1), "=r"(r2), "=r"(r3) : "r"(addr));
}
__device__ __forceinline__ void mma16816(float* c, uint32_t a0, uint32_t a1, uint32_t a2, uint32_t a3,
                                         uint32_t b0, uint32_t b1) {
    asm volatile("mma.sync.aligned.m16n8k16.row.col.f32.bf16.bf16.f32 "
                 "{%0,%1,%2,%3}, {%4,%5,%6,%7}, {%8,%9}, {%0,%1,%2,%3};"
                 : "+f"(c[0]), "+f"(c[1]), "+f"(c[2]), "+f"(c[3])
                 : "r"(a0), "r"(a1), "r"(a2), "r"(a3), "r"(b0), "r"(b1));
}
static __device__ __forceinline__ uint32_t sw128(uint32_t off) { return off ^ ((off >> 3) & 0x70); }

// ================= HMMA GEMM (bf16 3-product split, fp32 accum) =================
#define GTHREADS 256
#define KC 64
#define STAGE_BYTES 65536           // 4 arrays x 16KB (128 rows x 128B)
#define NSTAGE 3
#define GEMM_SMEM (NSTAGE * STAGE_BYTES + 1024)

__global__ void __launch_bounds__(GTHREADS)
gemm_mma_kernel(const bf16* __restrict__ Ahi, const bf16* __restrict__ Alo, long aBatch,
                const bf16* __restrict__ Bhi, const bf16* __restrict__ Blo, long bBatch,
                const float* __restrict__ bias, long biasBatch,
                float* __restrict__ C, long cBatch, int ldc,
                int M, int K, int reluEpi)
{
    extern __shared__ char smem[];
    const uint32_t S = (smem_u32(smem) + 1023) & ~1023u;

    const int bz = blockIdx.z;
    Ahi += (long)bz * aBatch;  Alo += (long)bz * aBatch;
    Bhi += (long)bz * bBatch;  Blo += (long)bz * bBatch;
    const float* bp = bias + (long)bz * biasBatch;
    C += (long)bz * cBatch;

    const int n0 = blockIdx.x * 128;
    const int m0 = blockIdx.y * 128;
    const int t  = threadIdx.x;
    const int wid = t >> 5, lid = t & 31;
    const int warp_m = wid & 3;
    const int warp_n = wid >> 2;
    const int T = K / KC;

    auto load_tile = [&](int kt, int stg) {
        const uint32_t sb = S + stg * STAGE_BYTES;
        const int kbase = kt * KC;
#pragma unroll
        for (int j = 0; j < 4; j++) {
            int cid = t + j * 256;
            int row = cid >> 3, c16 = cid & 7;
            uint32_t dsw = sw128((uint32_t)(row * 128 + c16 * 16));
            size_t aoff = (size_t)(m0 + row) * K + kbase + c16 * 8;
            bool ap = (m0 + row) < M;
            cpa16(sb + dsw,          Ahi + aoff, ap);
            cpa16(sb + 16384 + dsw,  Alo + aoff, ap);
            size_t boff = (size_t)(n0 + row) * K + kbase + c16 * 8;
            cpa16(sb + 32768 + dsw,  Bhi + boff, true);
            cpa16(sb + 49152 + dsw,  Blo + boff, true);
        }
        cpa_commit();
    };

    float acc[2][8][4];
#pragma unroll
    for (int i = 0; i < 2; i++)
#pragma unroll
        for (int j = 0; j < 8; j++)
#pragma unroll
            for (int q = 0; q < 4; q++) acc[i][j][q] = 0.f;

#pragma unroll
    for (int p = 0; p < NSTAGE; p++) {
        if (p < T) load_tile(p, p); else cpa_commit();
    }

    const int lrow = lid & 15;
    const int lhalf = (lid >> 4) * 16;

    for (int kt = 0; kt < T; kt++) {
        cpa_wait2();
        __syncthreads();
        const uint32_t sb = S + (kt % NSTAGE) * STAGE_BYTES;

#pragma unroll
        for (int kk = 0; kk < 4; kk++) {
            const int kb = kk * 32;
            uint32_t ah[2][4], al[2][4];
#pragma unroll
            for (int mf = 0; mf < 2; mf++) {
                int row = warp_m * 32 + mf * 16 + lrow;
                uint32_t off = sw128((uint32_t)(row * 128 + kb + lhalf));
                ldsm_x4(ah[mf][0], ah[mf][1], ah[mf][2], ah[mf][3], sb + off);
                ldsm_x4(al[mf][0], al[mf][1], al[mf][2], al[mf][3], sb + 16384 + off);
            }
            uint32_t bh[4][4], bl[4][4];
#pragma unroll
            for (int g = 0; g < 4; g++) {
                int row = warp_n * 64 + g * 16 + lrow;
                uint32_t off = sw128((uint32_t)(row * 128 + kb + lhalf));
                ldsm_x4(bh[g][0], bh[g][1], bh[g][2], bh[g][3], sb + 32768 + off);
                ldsm_x4(bl[g][0], bl[g][1], bl[g][2], bl[g][3], sb + 49152 + off);
            }
            // product-major ordering: acc reuse distance = 8 (no RAW chains)
#pragma unroll
            for (int mf = 0; mf < 2; mf++) {
#pragma unroll
                for (int nf = 0; nf < 8; nf++) {
                    int g = nf >> 1, od = nf & 1;
                    mma16816(acc[mf][nf], ah[mf][0], ah[mf][1], ah[mf][2], ah[mf][3],
                             od ? bh[g][1] : bh[g][0], od ? bh[g][3] : bh[g][2]);
                }
#pragma unroll
                for (int nf = 0; nf < 8; nf++) {
                    int g = nf >> 1, od = nf & 1;
                    mma16816(acc[mf][nf], ah[mf][0], ah[mf][1], ah[mf][2], ah[mf][3],
                             od ? bl[g][1] : bl[g][0], od ? bl[g][3] : bl[g][2]);
                }
#pragma unroll
                for (int nf = 0; nf < 8; nf++) {
                    int g = nf >> 1, od = nf & 1;
                    mma16816(acc[mf][nf], al[mf][0], al[mf][1], al[mf][2], al[mf][3],
                             od ? bh[g][1] : bh[g][0], od ? bh[g][3] : bh[g][2]);
                }
            }
        }
        __syncthreads();
        if (kt + NSTAGE < T) load_tile(kt + NSTAGE, kt % NSTAGE); else cpa_commit();
    }
    cpa_wait0();

    // ---- epilogue ----
#pragma unroll
    for (int mf = 0; mf < 2; mf++) {
        int rbase = m0 + warp_m * 32 + mf * 16 + (lid >> 2);
#pragma unroll
        for (int nf = 0; nf < 8; nf++) {
            int col = n0 + warp_n * 64 + nf * 8 + (lid & 3) * 2;
            float bx = __ldg(&bp[col]), by = __ldg(&bp[col + 1]);
            float v0 = acc[mf][nf][0] + bx, v1 = acc[mf][nf][1] + by;
            float v2 = acc[mf][nf][2] + bx, v3 = acc[mf][nf][3] + by;
            if (reluEpi) {
                v0 = fmaxf(v0, 0.f); v1 = fmaxf(v1, 0.f);
                v2 = fmaxf(v2, 0.f); v3 = fmaxf(v3, 0.f);
            }
            if (rbase < M)     *(float2*)&C[(size_t)rbase * ldc + col]       = make_float2(v0, v1);
            if (rbase + 8 < M) *(float2*)&C[(size_t)(rbase + 8) * ldc + col] = make_float2(v2, v3);
        }
    }
}

// ================= split / transpose kernels =================
__global__ void split_kernel(const float* __restrict__ in, bf16* __restrict__ hi,
                             bf16* __restrict__ lo, size_t n)
{
    size_t i = ((size_t)blockIdx.x * blockDim.x + threadIdx.x) * 4;
    if (i >= n) return;
    float4 v = *(const float4*)(in + i);
    bf16 h0 = __float2bfloat16(v.x), h1 = __float2bfloat16(v.y);
    bf16 h2 = __float2bfloat16(v.z), h3 = __float2bfloat16(v.w);
    hi[i] = h0; hi[i+1] = h1; hi[i+2] = h2; hi[i+3] = h3;
    lo[i]   = __float2bfloat16(v.x - __bfloat162float(h0));
    lo[i+1] = __float2bfloat16(v.y - __bfloat162float(h1));
    lo[i+2] = __float2bfloat16(v.z - __bfloat162float(h2));
    lo[i+3] = __float2bfloat16(v.w - __bfloat162float(h3));
}

__global__ void split_affine_kernel(const float* __restrict__ in,
                                    const float* __restrict__ sc, const float* __restrict__ sh,
                                    int ld, bf16* __restrict__ hi, bf16* __restrict__ lo, size_t n)
{
    size_t i = ((size_t)blockIdx.x * blockDim.x + threadIdx.x) * 4;
    if (i >= n) return;
    float4 v = *(const float4*)(in + i);
    int col = (int)(i % ld);
    int soff = (int)(i / ((size_t)ld * NNODE)) * ld + col;
    float4 s = *(const float4*)(sc + soff);
    float4 h = *(const float4*)(sh + soff);
    float w0 = fmaxf(fmaf(v.x, s.x, h.x), 0.f);
    float w1 = fmaxf(fmaf(v.y, s.y, h.y), 0.f);
    float w2 = fmaxf(fmaf(v.z, s.z, h.z), 0.f);
    float w3 = fmaxf(fmaf(v.w, s.w, h.w), 0.f);
    bf16 a0 = __float2bfloat16(w0), a1 = __float2bfloat16(w1);
    bf16 a2 = __float2bfloat16(w2), a3 = __float2bfloat16(w3);
    hi[i] = a0; hi[i+1] = a1; hi[i+2] = a2; hi[i+3] = a3;
    lo[i]   = __float2bfloat16(w0 - __bfloat162float(a0));
    lo[i+1] = __float2bfloat16(w1 - __bfloat162float(a1));
    lo[i+2] = __float2bfloat16(w2 - __bfloat162float(a2));
    lo[i+3] = __float2bfloat16(w3 - __bfloat162float(a3));
}

__global__ void tsplit_kernel(const float* __restrict__ W, long wBatch, int K, int Nn,
                              bf16* __restrict__ hi, bf16* __restrict__ lo, long oBatch)
{
    __shared__ float tile[32][33];
    const float* Wb = W + (long)blockIdx.z * wBatch;
    bf16* hib = hi + (long)blockIdx.z * oBatch;
    bf16* lob = lo + (long)blockIdx.z * oBatch;
    int nb = blockIdx.x * 32, kb = blockIdx.y * 32;
    int tx = threadIdx.x, ty = threadIdx.y;
#pragma unroll
    for (int r = 0; r < 32; r += 8)
        tile[ty + r][tx] = Wb[(size_t)(kb + ty + r) * Nn + nb + tx];
    __syncthreads();
#pragma unroll
    for (int r = 0; r < 32; r += 8) {
        float v = tile[tx][ty + r];
        bf16 h = __float2bfloat16(v);
        size_t o = (size_t)(nb + ty + r) * K + kb + tx;
        hib[o] = h;
        lob[o] = __float2bfloat16(v - __bfloat162float(h));
    }
}

// ================= BN statistics =================
__global__ void stats_part_kernel(const float* __restrict__ X, long xBatch, int ld, int M,
                                  float2* __restrict__ part)
{
    const int col = blockIdx.y * 256 + threadIdx.x;
    const float* Xb = X + (long)blockIdx.z * xBatch;
    const int rowsPer = (M + SROWS - 1) / SROWS;
    int r0 = blockIdx.x * rowsPer;
    int r1 = min(r0 + rowsPer, M);
    float s = 0.f, q = 0.f;
    for (int r = r0; r < r1; r++) {
        float v = __ldg(&Xb[(size_t)r * ld + col]);
        s += v; q = fmaf(v, v, q);
    }
    part[(size_t)blockIdx.x * HCW + blockIdx.z * ld + col] = make_float2(s, q);
}

__global__ void finalize_bn_kernel(const float2* __restrict__ part,
                                   const float* __restrict__ g, const float* __restrict__ be,
                                   float* __restrict__ sc, float* __restrict__ sh, float invN)
{
    int i = blockIdx.x * blockDim.x + threadIdx.x;
    float s = 0.f, q = 0.f;
#pragma unroll 8
    for (int r = 0; r < SROWS; r++) {
        float2 p = part[(size_t)r * HCW + i];
        s += p.x; q += p.y;
    }
    float mu  = s * invN;
    float var = q * invN - mu * mu;
    float sl = g[i] * rsqrtf(var + EPSBN);
    sc[i] = sl;
    sh[i] = be[i] - mu * sl;
}

// ================= KAN =================
__device__ __forceinline__ void bspline8(float x, float bs[11])
{
#pragma unroll
    for (int j = 0; j < 11; j++) {
        float gl = (float)(j - 3) * 0.4f - 1.0f;
        float gr = (float)(j - 2) * 0.4f - 1.0f;
        bs[j] = (x >= gl && x < gr) ? 1.0f : 0.0f;
    }
#pragma unroll
    for (int p = 1; p <= 3; p++) {
        float inv = 1.0f / (0.4f * (float)p);
#pragma unroll
        for (int j = 0; j < 11 - p; j++) {
            float gj   = (float)(j - 3) * 0.4f - 1.0f;
            float gjp1 = (float)(j + p - 2) * 0.4f - 1.0f;
            bs[j] = ((x - gj) * bs[j] + (gjp1 - x) * bs[j + 1]) * inv;
        }
    }
}

// KAN layer 1 (1024 -> 32): 4 threads per node, 8 outputs each
__global__ void __launch_bounds__(128)
kan1_kernel(const float* __restrict__ X, const float* __restrict__ bw,
            const float* __restrict__ sw, const float* __restrict__ sc,
            float* __restrict__ out, int n)
{
    int gid = blockIdx.x * blockDim.x + threadIdx.x;
    int node = gid >> 2, og = gid & 3;
    if (node >= n) return;
    float acc[8];
#pragma unroll
    for (int j = 0; j < 8; j++) acc[j] = 0.f;

    for (int i = 0; i < F1D; i++) {
        float x = __ldg(&X[(size_t)node * F1D + i]);
        float bs[11];
        bspline8(x, bs);
        float s = x / (1.0f + expf(-x));
#pragma unroll
        for (int j = 0; j < 8; j++) {
            int o = og * 8 + j;
            const float4* swp = (const float4*)(sw + ((size_t)o * F1D + i) * 8);
            float4 w0 = __ldg(&swp[0]);
            float4 w1 = __ldg(&swp[1]);
            float sp = bs[0] * w0.x + bs[1] * w0.y + bs[2] * w0.z + bs[3] * w0.w
                     + bs[4] * w1.x + bs[5] * w1.y + bs[6] * w1.z + bs[7] * w1.w;
            acc[j] = fmaf(s, __ldg(&bw[(size_t)o * F1D + i]),
                     fmaf(sp, __ldg(&sc[(size_t)o * F1D + i]), acc[j]));
        }
    }
#pragma unroll
    for (int j = 0; j < 8; j++) out[(size_t)node * KO1 + og * 8 + j] = acc[j];
}

template <int IN, int OUTC>
__global__ void __launch_bounds__(128)
kan_kernel(const float* __restrict__ X, const float* __restrict__ bw,
           const float* __restrict__ sw, const float* __restrict__ sc,
           float* __restrict__ out, int n)
{
    int node = blockIdx.x * blockDim.x + threadIdx.x;
    if (node >= n) return;
    float acc[OUTC];
#pragma unroll
    for (int o = 0; o < OUTC; o++) acc[o] = 0.f;

    for (int i = 0; i < IN; i++) {
        float x = __ldg(&X[(size_t)node * IN + i]);
        float bs[11];
        bspline8(x, bs);
        float s = x / (1.0f + expf(-x));
#pragma unroll
        for (int o = 0; o < OUTC; o++) {
            const float4* swp = (const float4*)(sw + ((size_t)o * IN + i) * 8);
            float4 w0 = __ldg(&swp[0]);
            float4 w1 = __ldg(&swp[1]);
            float sp = bs[0] * w0.x + bs[1] * w0.y + bs[2] * w0.z + bs[3] * w0.w
                     + bs[4] * w1.x + bs[5] * w1.y + bs[6] * w1.z + bs[7] * w1.w;
            acc[o] = fmaf(s, __ldg(&bw[(size_t)o * IN + i]),
                     fmaf(sp, __ldg(&sc[(size_t)o * IN + i]), acc[o]));
        }
    }
#pragma unroll
    for (int o = 0; o < OUTC; o++) out[(size_t)node * OUTC + o] = acc[o];
}

// ================= launch =================
extern "C" void kernel_launch(void* const* d_in, const int* in_sizes, int n_in,
                              void* d_out, int out_size)
{
    const float* x   = (const float*)d_in[0];
    const float* W1  = (const float*)d_in[3];
    const float* b1  = (const float*)d_in[4];
    const float* gm1 = (const float*)d_in[5];
    const float* bt1 = (const float*)d_in[6];
    const float* W2  = (const float*)d_in[7];
    const float* b2  = (const float*)d_in[8];
    const float* gm2 = (const float*)d_in[9];
    const float* bt2 = (const float*)d_in[10];
    const float* Wf  = (const float*)d_in[11];
    const float* bf  = (const float*)d_in[12];
    const float* bw1 = (const float*)d_in[13];
    const float* sw1 = (const float*)d_in[14];
    const float* sc1 = (const float*)d_in[15];
    const float* bw2 = (const float*)d_in[16];
    const float* sw2 = (const float*)d_in[17];
    const float* sc2 = (const float*)d_in[18];

    float *h1, *hc, *f, *f2, *sca1, *shf1, *sca2, *shf2;
    float2 *part;
    bf16 *xhi, *xlo, *h1hi, *h1lo, *hchi, *hclo, *w1hi, *w1lo, *w2hi, *w2lo, *wfhi, *wflo;
    cudaGetSymbolAddress((void**)&h1, g_h1);   cudaGetSymbolAddress((void**)&hc, g_hc);
    cudaGetSymbolAddress((void**)&f, g_f);     cudaGetSymbolAddress((void**)&f2, g_f2);
    cudaGetSymbolAddress((void**)&xhi, g_xhi); cudaGetSymbolAddress((void**)&xlo, g_xlo);
    cudaGetSymbolAddress((void**)&h1hi, g_h1hi); cudaGetSymbolAddress((void**)&h1lo, g_h1lo);
    cudaGetSymbolAddress((void**)&hchi, g_hchi); cudaGetSymbolAddress((void**)&hclo, g_hclo);
    cudaGetSymbolAddress((void**)&w1hi, g_w1hi); cudaGetSymbolAddress((void**)&w1lo, g_w1lo);
    cudaGetSymbolAddress((void**)&w2hi, g_w2hi); cudaGetSymbolAddress((void**)&w2lo, g_w2lo);
    cudaGetSymbolAddress((void**)&wfhi, g_wfhi); cudaGetSymbolAddress((void**)&wflo, g_wflo);
    cudaGetSymbolAddress((void**)&part, g_part);
    cudaGetSymbolAddress((void**)&sca1, g_scale1); cudaGetSymbolAddress((void**)&shf1, g_shift1);
    cudaGetSymbolAddress((void**)&sca2, g_scale2); cudaGetSymbolAddress((void**)&shf2, g_shift2);

    cudaFuncSetAttribute(gemm_mma_kernel, cudaFuncAttributeMaxDynamicSharedMemorySize, GEMM_SMEM);

    const int mT = (NNODE + 127) / 128;   // 157
    dim3 tb(32, 8);

    // 1: x -> hi/lo
    {
        size_t n = (size_t)BATCH * NNODE * FEATD;
        split_kernel<<<(unsigned)((n/4 + 255)/256), 256>>>(x, xhi, xlo, n);
    }
    // 2-3: W1, W2 transpose+split
    tsplit_kernel<<<dim3(HDIM/32, FEATD/32, BATCH), tb>>>(W1, (long)FEATD*HDIM, FEATD, HDIM, w1hi, w1lo, (long)HDIM*FEATD);
    tsplit_kernel<<<dim3(HDIM/32, HDIM/32, BATCH), tb>>>(W2, (long)HDIM*HDIM, HDIM, HDIM, w2hi, w2lo, (long)HDIM*HDIM);
    // 4: Wf transpose+split
    tsplit_kernel<<<dim3(F1D/32, HCW/32, 1), tb>>>(Wf, 0, HCW, F1D, wfhi, wflo, 0);

    // 5-6: GEMM1 in two half-batch launches (also lands in the ncu -s 5 window)
    gemm_mma_kernel<<<dim3(HDIM/128, mT, 4), GTHREADS, GEMM_SMEM>>>(
        xhi, xlo, (long)NNODE*FEATD, w1hi, w1lo, (long)HDIM*FEATD,
        b1, HDIM, h1, (long)NNODE*HDIM, HDIM, NNODE, FEATD, 0);
    gemm_mma_kernel<<<dim3(HDIM/128, mT, 4), GTHREADS, GEMM_SMEM>>>(
        xhi + 4l*NNODE*FEATD, xlo + 4l*NNODE*FEATD, (long)NNODE*FEATD,
        w1hi + 4l*HDIM*FEATD, w1lo + 4l*HDIM*FEATD, (long)HDIM*FEATD,
        b1 + 4l*HDIM, HDIM, h1 + 4l*NNODE*HDIM, (long)NNODE*HDIM, HDIM, NNODE, FEATD, 0);

    // BN1
    stats_part_kernel<<<dim3(SROWS, HDIM/256, BATCH), 256>>>(h1, (long)NNODE*HDIM, HDIM, NNODE, part);
    finalize_bn_kernel<<<HCW/256, 256>>>(part, gm1, bt1, sca1, shf1, 1.0f/NNODE);
    {
        size_t n = (size_t)BATCH * NNODE * HDIM;
        split_affine_kernel<<<(unsigned)((n/4 + 255)/256), 256>>>(h1, sca1, shf1, HDIM, h1hi, h1lo, n);
    }

    // GEMM2
    gemm_mma_kernel<<<dim3(HDIM/128, mT, BATCH), GTHREADS, GEMM_SMEM>>>(
        h1hi, h1lo, (long)NNODE*HDIM, w2hi, w2lo, (long)HDIM*HDIM,
        b2, HDIM, hc, (long)HDIM, HCW, NNODE, HDIM, 0);

    // BN2
    stats_part_kernel<<<dim3(SROWS, HCW/256, 1), 256>>>(hc, 0, HCW, NNODE, part);
    finalize_bn_kernel<<<HCW/256, 256>>>(part, gm2, bt2, sca2, shf2, 1.0f/NNODE);
    {
        size_t n = (size_t)NNODE * HCW;
        split_affine_kernel<<<(unsigned)((n/4 + 255)/256), 256>>>(hc, sca2, shf2, HCW, hchi, hclo, n);
    }

    // GEMM3
    gemm_mma_kernel<<<dim3(F1D/128, mT, 1), GTHREADS, GEMM_SMEM>>>(
        hchi, hclo, 0, wfhi, wflo, 0,
        bf, 0, f, 0, F1D, NNODE, HCW, 1);

    // KAN
    kan1_kernel<<<(NNODE * 4 + 127)/128, 128>>>(f, bw1, sw1, sc1, f2, NNODE);
    kan_kernel<KO1, KO2><<<(NNODE + 127)/128, 128>>>(f2, bw2, sw2, sc2, (float*)d_out, NNODE);
}